// round 9
// baseline (speedup 1.0000x reference)
#include <cuda_runtime.h>
#include <cuda_bf16.h>
#include <cstdint>

#define PP 1024
#define NROW 16384
#define TILE_M 128
#define TILE_N 128
#define KC 64
#define NCH (PP / KC)          // 16 k-chunks
#define NSLOT 32               // 8 col-blocks * 4 n-warps

// smem stage layout (bytes) — 2 stages of 64KB
#define AHI 0
#define ALO 16384
#define BHI 32768
#define BLO 49152
#define STAGE_BYTES 65536
#define SMEM_TOTAL (2 * STAGE_BYTES)   // 128 KB

// Scratch (static __device__ — no allocation allowed)
__device__ __align__(16) __nv_bfloat16 g_Whi[(size_t)PP * PP];   // W^T layout: [n][k]
__device__ __align__(16) __nv_bfloat16 g_Wlo[(size_t)PP * PP];
__device__ float g_ypart[(size_t)NSLOT * NROW];

// ---------------- helpers ----------------
__device__ __forceinline__ uint32_t smem_u32(const void* p) {
    uint32_t a;
    asm("{ .reg .u64 t; cvta.to.shared.u64 t, %1; cvt.u32.u64 %0, t; }" : "=r"(a) : "l"(p));
    return a;
}
// 128B rows of bf16 (64 elems). 16B chunk swizzle: chunk ^= (row & 7)
__device__ __forceinline__ uint32_t sw(int row, int ch) {
    return (uint32_t)(row * 128 + ((ch ^ (row & 7)) << 4));
}
__device__ __forceinline__ void cp16(uint32_t dst, const void* src) {
    asm volatile("cp.async.cg.shared.global [%0], [%1], 16;" :: "r"(dst), "l"(src) : "memory");
}
__device__ __forceinline__ void ldmx4(uint32_t* r, uint32_t addr) {
    asm volatile("ldmatrix.sync.aligned.m8n8.x4.shared.b16 {%0,%1,%2,%3}, [%4];"
                 : "=r"(r[0]), "=r"(r[1]), "=r"(r[2]), "=r"(r[3]) : "r"(addr));
}
__device__ __forceinline__ void mma16816(float* c, const uint32_t* a, const uint32_t* b) {
    asm volatile(
        "mma.sync.aligned.m16n8k16.row.col.f32.bf16.bf16.f32 "
        "{%0,%1,%2,%3}, {%4,%5,%6,%7}, {%8,%9}, {%0,%1,%2,%3};"
        : "+f"(c[0]), "+f"(c[1]), "+f"(c[2]), "+f"(c[3])
        : "r"(a[0]), "r"(a[1]), "r"(a[2]), "r"(a[3]), "r"(b[0]), "r"(b[1]));
}

// ---------------------------------------------------------------------------
// Prep: scatter theta into W^T [n][k] (nonzero for n>k), split bf16 hi/lo
// ---------------------------------------------------------------------------
__global__ void build_W_kernel(const float* __restrict__ theta) {
    int idx = blockIdx.x * blockDim.x + threadIdx.x;    // over P*P
    int n = idx >> 10, k = idx & (PP - 1);
    float v = 0.0f;
    if (n > k) v = theta[k * PP - ((k * (k + 1)) >> 1) + (n - k - 1)];
    __nv_bfloat16 h = __float2bfloat16(v);
    __nv_bfloat16 l = __float2bfloat16(v - __bfloat162float(h));
    g_Whi[idx] = h;
    g_Wlo[idx] = l;
}

// ---------------------------------------------------------------------------
// Main: bf16x3 mma.sync GEMM (128x128 tile) + fused (C+beta)·x rowdot epilogue.
// X is converted fp32 -> bf16 hi/lo IN-KERNEL (no separate split pass):
// each thread prefetches 32 fp32 (half a row of the A chunk) via LDG, converts,
// and STS's the swizzled hi/lo tiles. One __syncthreads per chunk.
// Triangular chunk skip (nch_eff = 2*(bn+1)) + LPT heavy-first ordering.
// ---------------------------------------------------------------------------
__global__ __launch_bounds__(256, 1)
void gemm_rowdot_mma(const float* __restrict__ X, const float* __restrict__ beta) {
    extern __shared__ char smem[];
    const uint32_t sbase = smem_u32(smem);
    const int tid = threadIdx.x;
    const int l = tid & 31;
    const int wid = tid >> 5;
    const int wm = wid & 1;        // 2 m-warps
    const int wn = wid >> 1;       // 4 n-warps
    const int m_base = wm * 64;
    const int n_base = wn * 32;

    // heavy-first decode: first 128 CTAs take bn=7, next 128 bn=6, ...
    const int bn = 7 - (int)(blockIdx.x >> 7);
    const int bx = (int)(blockIdx.x & 127);
    const int i0 = bx * TILE_M;
    const int n0 = bn * TILE_N;
    const int nch_eff = 2 * (bn + 1);   // <= NCH

    // conversion assignment: thread -> (row, half-row of 32 k-elems)
    const int xrow = tid >> 1;
    const int xhalf = tid & 1;
    const float* xsrc_base = X + (size_t)(i0 + xrow) * PP + xhalf * 32;

    float acc[4][4][4];            // [mi][ni][frag]
#pragma unroll
    for (int mi = 0; mi < 4; ++mi)
#pragma unroll
        for (int ni = 0; ni < 4; ++ni)
#pragma unroll
            for (int q = 0; q < 4; ++q) acc[mi][ni][q] = 0.0f;

    // --- B-tile async load for chunk c (8 cp16 per thread) ---
    auto load_W = [&](int c) {
        const uint32_t stg = sbase + (uint32_t)(c & 1) * STAGE_BYTES;
        const int k0 = c * KC;
#pragma unroll
        for (int it = 0; it < 4; ++it) {
            int u = tid + it * 256;
            int row = u >> 3, ch = u & 7;
            uint32_t d = sw(row, ch);
            size_t bsrc = (size_t)(n0 + row) * PP + k0 + ch * 8;
            cp16(stg + BHI + d, g_Whi + bsrc);
            cp16(stg + BLO + d, g_Wlo + bsrc);
        }
        asm volatile("cp.async.commit_group;" ::: "memory");
    };
    // --- fp32 X prefetch for chunk c into registers ---
    auto load_X = [&](int c, float4* xf) {
        const float4* s = (const float4*)(xsrc_base + c * KC);
#pragma unroll
        for (int q = 0; q < 8; ++q) xf[q] = s[q];
    };
    // --- convert regs -> swizzled bf16 hi/lo A tiles in stage of chunk c ---
    auto convert_A = [&](int c, const float4* xf) {
        const uint32_t stg = sbase + (uint32_t)(c & 1) * STAGE_BYTES;
#pragma unroll
        for (int q = 0; q < 4; ++q) {
            float4 a = xf[2 * q], b = xf[2 * q + 1];
            float f[8] = {a.x, a.y, a.z, a.w, b.x, b.y, b.z, b.w};
            uint32_t hi[4], lo[4];
#pragma unroll
            for (int e = 0; e < 4; ++e) {
                __nv_bfloat16 h0 = __float2bfloat16(f[2 * e]);
                __nv_bfloat16 h1 = __float2bfloat16(f[2 * e + 1]);
                __nv_bfloat16 l0 = __float2bfloat16(f[2 * e] - __bfloat162float(h0));
                __nv_bfloat16 l1 = __float2bfloat16(f[2 * e + 1] - __bfloat162float(h1));
                hi[e] = (uint32_t)__bfloat16_as_ushort(h0) | ((uint32_t)__bfloat16_as_ushort(h1) << 16);
                lo[e] = (uint32_t)__bfloat16_as_ushort(l0) | ((uint32_t)__bfloat16_as_ushort(l1) << 16);
            }
            uint32_t d = sw(xrow, xhalf * 4 + q);
            *(uint4*)(smem + ((uint32_t)(c & 1) * STAGE_BYTES) + AHI + d) = make_uint4(hi[0], hi[1], hi[2], hi[3]);
            *(uint4*)(smem + ((uint32_t)(c & 1) * STAGE_BYTES) + ALO + d) = make_uint4(lo[0], lo[1], lo[2], lo[3]);
        }
        (void)stg;
    };

    float4 xf[8];
    load_X(0, xf);
    load_W(0);

    for (int c = 0; c < nch_eff; ++c) {
        // wait for this chunk's B tiles (only one cp.async group ever in flight)
        asm volatile("cp.async.wait_group 0;" ::: "memory");
        convert_A(c, xf);
        // barrier: (a) A/B tiles of chunk c visible to all warps,
        // (b) all warps finished chunk c-1 -> stage (c+1)&1 is reusable
        __syncthreads();
        if (c + 1 < nch_eff) {
            load_W(c + 1);
            load_X(c + 1, xf);
        }

        const uint32_t stg = sbase + (uint32_t)(c & 1) * STAGE_BYTES;
#pragma unroll
        for (int ks = 0; ks < 4; ++ks) {
            uint32_t ahi[4][4], alo[4][4], bhi[4][2], blo[4][2];
            // A fragments: lanes 0-15 rows r, k-lo; lanes 16-31 rows r, k-hi
            {
                int r = l & 15, kh = l >> 4;
                int ch = ks * 2 + kh;
#pragma unroll
                for (int mi = 0; mi < 4; ++mi) {
                    uint32_t ad = sw(m_base + mi * 16 + r, ch);
                    ldmx4(ahi[mi], stg + AHI + ad);
                    ldmx4(alo[mi], stg + ALO + ad);
                }
            }
            // B fragments: 2 x ldmatrix.x4, each covers 2 n8-tiles x full k16
            {
                int nr_off = ((l >> 4) << 3) + (l & 7);
                int ch = ks * 2 + ((l >> 3) & 1);
#pragma unroll
                for (int np = 0; np < 2; ++np) {
                    uint32_t bd = sw(n_base + np * 16 + nr_off, ch);
                    uint32_t r4[4];
                    ldmx4(r4, stg + BHI + bd);
                    bhi[np * 2][0] = r4[0]; bhi[np * 2][1] = r4[1];
                    bhi[np * 2 + 1][0] = r4[2]; bhi[np * 2 + 1][1] = r4[3];
                    ldmx4(r4, stg + BLO + bd);
                    blo[np * 2][0] = r4[0]; blo[np * 2][1] = r4[1];
                    blo[np * 2 + 1][0] = r4[2]; blo[np * 2 + 1][1] = r4[3];
                }
            }
#pragma unroll
            for (int mi = 0; mi < 4; ++mi)
#pragma unroll
                for (int ni = 0; ni < 4; ++ni) {
                    mma16816(acc[mi][ni], ahi[mi], bhi[ni]);
                    mma16816(acc[mi][ni], ahi[mi], blo[ni]);
                    mma16816(acc[mi][ni], alo[mi], bhi[ni]);
                }
        }
        __syncthreads();
    }

    // --- fused epilogue: part_r = sum_c (C[r][c] + beta[c]) * X[r][c] ---
#pragma unroll
    for (int mi = 0; mi < 4; ++mi) {
        int r0 = i0 + m_base + mi * 16 + (l >> 2);
        int r1 = r0 + 8;
        float p0 = 0.0f, p1 = 0.0f;
#pragma unroll
        for (int ni = 0; ni < 4; ++ni) {
            int cc = n0 + n_base + ni * 8 + (l & 3) * 2;
            float2 bv  = *(const float2*)&beta[cc];
            float2 x0  = *(const float2*)&X[(size_t)r0 * PP + cc];
            float2 x1  = *(const float2*)&X[(size_t)r1 * PP + cc];
            p0 = fmaf(acc[mi][ni][0] + bv.x, x0.x, p0);
            p0 = fmaf(acc[mi][ni][1] + bv.y, x0.y, p0);
            p1 = fmaf(acc[mi][ni][2] + bv.x, x1.x, p1);
            p1 = fmaf(acc[mi][ni][3] + bv.y, x1.y, p1);
        }
        // reduce over the 4 lanes sharing a row (low 2 lane bits)
        p0 += __shfl_xor_sync(0xffffffffu, p0, 1);
        p0 += __shfl_xor_sync(0xffffffffu, p0, 2);
        p1 += __shfl_xor_sync(0xffffffffu, p1, 1);
        p1 += __shfl_xor_sync(0xffffffffu, p1, 2);
        if ((l & 3) == 0) {
            int slot = bn * 4 + wn;
            g_ypart[(size_t)slot * NROW + r0] = p0;
            g_ypart[(size_t)slot * NROW + r1] = p1;
        }
    }
}

// ---------------------------------------------------------------------------
// Final: y[i] = beta0 + sum of 32 partials
// ---------------------------------------------------------------------------
__global__ void reduce_kernel(const float* __restrict__ beta0, float* __restrict__ y) {
    int i = blockIdx.x * blockDim.x + threadIdx.x;
    if (i >= NROW) return;
    float s = beta0[0];
#pragma unroll
    for (int g = 0; g < NSLOT; ++g) s += g_ypart[(size_t)g * NROW + i];
    y[i] = s;
}

extern "C" void kernel_launch(void* const* d_in, const int* in_sizes, int n_in,
                              void* d_out, int out_size) {
    const float* X     = (const float*)d_in[0];
    const float* beta0 = (const float*)d_in[1];
    const float* beta  = (const float*)d_in[2];
    const float* theta = (const float*)d_in[3];
    float* y = (float*)d_out;

    cudaFuncSetAttribute(gemm_rowdot_mma, cudaFuncAttributeMaxDynamicSharedMemorySize, SMEM_TOTAL);

    build_W_kernel<<<(PP * PP + 255) / 256, 256>>>(theta);

    gemm_rowdot_mma<<<1024, 256, SMEM_TOTAL>>>(X, beta);

    reduce_kernel<<<(NROW + 255) / 256, 256>>>(beta0, y);
}

// round 10
// speedup vs baseline: 1.3257x; 1.3257x over previous
#include <cuda_runtime.h>
#include <cuda_bf16.h>
#include <cstdint>

#define PP 1024
#define NROW 16384
#define TILE_M 128
#define TILE_N 128
#define KC 64
#define NCH (PP / KC)          // 16 k-chunks
#define NSLOT 8                // 1 slot per n-tile (CTA-reduced)

// smem stage layout (bytes)
#define AHI 0
#define ALO 16384
#define BHI 32768
#define BLO 49152
#define STAGE_BYTES 65536
#define SMEM_TOTAL (2 * STAGE_BYTES)   // 128 KB

// prep kernel split point: X-blocks then W-blocks
#define XBLK (NROW * PP / 8 / 256)     // 8192
#define WBLK (PP * PP / 4 / 256)       // 1024

// Scratch (static __device__ — no allocation allowed)
__device__ __align__(16) __nv_bfloat16 g_Xhi[(size_t)NROW * PP];
__device__ __align__(16) __nv_bfloat16 g_Xlo[(size_t)NROW * PP];
__device__ __align__(16) __nv_bfloat16 g_Whi[(size_t)PP * PP];   // W^T layout: [n][k]
__device__ __align__(16) __nv_bfloat16 g_Wlo[(size_t)PP * PP];
__device__ float g_ypart[(size_t)NSLOT * NROW];

// ---------------- helpers ----------------
__device__ __forceinline__ uint32_t smem_u32(const void* p) {
    uint32_t a;
    asm("{ .reg .u64 t; cvta.to.shared.u64 t, %1; cvt.u32.u64 %0, t; }" : "=r"(a) : "l"(p));
    return a;
}
// 128B rows of bf16 (64 elems). 16B chunk swizzle: chunk ^= (row & 7)
__device__ __forceinline__ uint32_t sw(int row, int ch) {
    return (uint32_t)(row * 128 + ((ch ^ (row & 7)) << 4));
}
__device__ __forceinline__ void cp16(uint32_t dst, const void* src) {
    asm volatile("cp.async.cg.shared.global [%0], [%1], 16;" :: "r"(dst), "l"(src) : "memory");
}
__device__ __forceinline__ void ldmx4(uint32_t* r, uint32_t addr) {
    asm volatile("ldmatrix.sync.aligned.m8n8.x4.shared.b16 {%0,%1,%2,%3}, [%4];"
                 : "=r"(r[0]), "=r"(r[1]), "=r"(r[2]), "=r"(r[3]) : "r"(addr));
}
__device__ __forceinline__ void mma16816(float* c, const uint32_t* a, const uint32_t* b) {
    asm volatile(
        "mma.sync.aligned.m16n8k16.row.col.f32.bf16.bf16.f32 "
        "{%0,%1,%2,%3}, {%4,%5,%6,%7}, {%8,%9}, {%0,%1,%2,%3};"
        : "+f"(c[0]), "+f"(c[1]), "+f"(c[2]), "+f"(c[3])
        : "r"(a[0]), "r"(a[1]), "r"(a[2]), "r"(a[3]), "r"(b[0]), "r"(b[1]));
}
__device__ __forceinline__ void split2(float a, float b, uint32_t& hi, uint32_t& lo) {
    __nv_bfloat16 h0 = __float2bfloat16(a);
    __nv_bfloat16 h1 = __float2bfloat16(b);
    __nv_bfloat16 l0 = __float2bfloat16(a - __bfloat162float(h0));
    __nv_bfloat16 l1 = __float2bfloat16(b - __bfloat162float(h1));
    hi = (uint32_t)__bfloat16_as_ushort(h0) | ((uint32_t)__bfloat16_as_ushort(h1) << 16);
    lo = (uint32_t)__bfloat16_as_ushort(l0) | ((uint32_t)__bfloat16_as_ushort(l1) << 16);
}

// ---------------------------------------------------------------------------
// Fused prep: blocks [0, XBLK) split X (8 floats/thread, 16B stores);
// blocks [XBLK, XBLK+WBLK) scatter theta into W^T and split (4 elems/thread).
// One launch -> the two bandwidth-bound passes overlap across SMs.
// ---------------------------------------------------------------------------
__global__ void prep_kernel(const float* __restrict__ X,
                            const float* __restrict__ theta) {
    if (blockIdx.x < XBLK) {
        size_t idx = (size_t)blockIdx.x * 256 + threadIdx.x;   // over N*P/8
        float4 v0 = reinterpret_cast<const float4*>(X)[idx * 2];
        float4 v1 = reinterpret_cast<const float4*>(X)[idx * 2 + 1];
        float f[8] = {v0.x, v0.y, v0.z, v0.w, v1.x, v1.y, v1.z, v1.w};
        uint32_t hi[4], lo[4];
#pragma unroll
        for (int q = 0; q < 4; ++q) split2(f[2 * q], f[2 * q + 1], hi[q], lo[q]);
        reinterpret_cast<uint4*>(g_Xhi)[idx] = make_uint4(hi[0], hi[1], hi[2], hi[3]);
        reinterpret_cast<uint4*>(g_Xlo)[idx] = make_uint4(lo[0], lo[1], lo[2], lo[3]);
    } else {
        int idx4 = (int)(blockIdx.x - XBLK) * 256 + threadIdx.x;  // over P*P/4
        int base = idx4 * 4;
        int n = base >> 10;
        int k0 = base & (PP - 1);     // 4 consecutive k, same n
        uint32_t hi[2], lo[2];
#pragma unroll
        for (int q = 0; q < 2; ++q) {
            float f[2];
#pragma unroll
            for (int e = 0; e < 2; ++e) {
                int k = k0 + q * 2 + e;
                f[e] = (n > k) ? theta[k * PP - ((k * (k + 1)) >> 1) + (n - k - 1)] : 0.0f;
            }
            split2(f[0], f[1], hi[q], lo[q]);
        }
        reinterpret_cast<uint2*>(g_Whi + base)[0] = make_uint2(hi[0], hi[1]);
        reinterpret_cast<uint2*>(g_Wlo + base)[0] = make_uint2(lo[0], lo[1]);
    }
}

// ---------------------------------------------------------------------------
// Main: bf16x3 mma.sync GEMM (128x128 tile) + fused (C+beta)·x rowdot epilogue.
// Triangular chunk skip (nch_eff = 2*(bn+1)); LPT heavy-first ordering;
// epilogue combines the 4 n-warps in smem -> one ypart slot per CTA.
// ---------------------------------------------------------------------------
__global__ __launch_bounds__(256, 1)
void gemm_rowdot_mma(const float* __restrict__ X, const float* __restrict__ beta) {
    extern __shared__ char smem[];
    const uint32_t sbase = smem_u32(smem);
    const int tid = threadIdx.x;
    const int l = tid & 31;
    const int wid = tid >> 5;
    const int wm = wid & 1;        // 2 m-warps
    const int wn = wid >> 1;       // 4 n-warps
    const int m_base = wm * 64;
    const int n_base = wn * 32;

    // heavy-first decode: first 128 CTAs take bn=7, next 128 bn=6, ...
    const int bn = 7 - (int)(blockIdx.x >> 7);
    const int bx = (int)(blockIdx.x & 127);
    const int i0 = bx * TILE_M;
    const int n0 = bn * TILE_N;
    const int nch_eff = 2 * (bn + 1);   // <= NCH

    float acc[4][4][4];            // [mi][ni][frag]
#pragma unroll
    for (int mi = 0; mi < 4; ++mi)
#pragma unroll
        for (int ni = 0; ni < 4; ++ni)
#pragma unroll
            for (int q = 0; q < 4; ++q) acc[mi][ni][q] = 0.0f;

    // --- async load of one stage: 4 tiles x 1024 chunks of 16B ---
    auto load_stage = [&](int c) {
        const uint32_t stg = sbase + (uint32_t)(c & 1) * STAGE_BYTES;
        const int k0 = c * KC;
#pragma unroll
        for (int it = 0; it < 4; ++it) {
            int u = tid + it * 256;
            int row = u >> 3, ch = u & 7;
            uint32_t d = sw(row, ch);
            size_t asrc = (size_t)(i0 + row) * PP + k0 + ch * 8;
            size_t bsrc = (size_t)(n0 + row) * PP + k0 + ch * 8;
            cp16(stg + AHI + d, g_Xhi + asrc);
            cp16(stg + ALO + d, g_Xlo + asrc);
            cp16(stg + BHI + d, g_Whi + bsrc);
            cp16(stg + BLO + d, g_Wlo + bsrc);
        }
        asm volatile("cp.async.commit_group;" ::: "memory");
    };

    load_stage(0);

    for (int c = 0; c < nch_eff; ++c) {
        if (c + 1 < nch_eff) {
            load_stage(c + 1);
            asm volatile("cp.async.wait_group 1;" ::: "memory");
        } else {
            asm volatile("cp.async.wait_group 0;" ::: "memory");
        }
        __syncthreads();

        const uint32_t stg = sbase + (uint32_t)(c & 1) * STAGE_BYTES;
#pragma unroll
        for (int ks = 0; ks < 4; ++ks) {
            uint32_t ahi[4][4], alo[4][4], bhi[4][2], blo[4][2];
            // A fragments: lanes 0-15 rows r, k-lo; lanes 16-31 rows r, k-hi
            {
                int r = l & 15, kh = l >> 4;
                int ch = ks * 2 + kh;
#pragma unroll
                for (int mi = 0; mi < 4; ++mi) {
                    uint32_t ad = sw(m_base + mi * 16 + r, ch);
                    ldmx4(ahi[mi], stg + AHI + ad);
                    ldmx4(alo[mi], stg + ALO + ad);
                }
            }
            // B fragments: 2 x ldmatrix.x4, each covers 2 n8-tiles x full k16
            {
                int nr_off = ((l >> 4) << 3) + (l & 7);
                int ch = ks * 2 + ((l >> 3) & 1);
#pragma unroll
                for (int np = 0; np < 2; ++np) {
                    uint32_t bd = sw(n_base + np * 16 + nr_off, ch);
                    uint32_t r4[4];
                    ldmx4(r4, stg + BHI + bd);
                    bhi[np * 2][0] = r4[0]; bhi[np * 2][1] = r4[1];
                    bhi[np * 2 + 1][0] = r4[2]; bhi[np * 2 + 1][1] = r4[3];
                    ldmx4(r4, stg + BLO + bd);
                    blo[np * 2][0] = r4[0]; blo[np * 2][1] = r4[1];
                    blo[np * 2 + 1][0] = r4[2]; blo[np * 2 + 1][1] = r4[3];
                }
            }
#pragma unroll
            for (int mi = 0; mi < 4; ++mi)
#pragma unroll
                for (int ni = 0; ni < 4; ++ni) {
                    mma16816(acc[mi][ni], ahi[mi], bhi[ni]);
                    mma16816(acc[mi][ni], ahi[mi], blo[ni]);
                    mma16816(acc[mi][ni], alo[mi], bhi[ni]);
                }
        }
        __syncthreads();
    }

    // --- fused epilogue: part_r = sum_c (C[r][c] + beta[c]) * X[r][c] ---
    // Per-warp partials land in smem [wn][128 tile rows]; then 128 threads
    // sum the 4 n-warp contributions and write ONE ypart slot per CTA.
    float* sarr = (float*)smem;    // 4*128 floats (loop's final sync makes reuse safe)
#pragma unroll
    for (int mi = 0; mi < 4; ++mi) {
        int tr0 = m_base + mi * 16 + (l >> 2);
        int tr1 = tr0 + 8;
        int r0 = i0 + tr0;
        int r1 = i0 + tr1;
        float p0 = 0.0f, p1 = 0.0f;
#pragma unroll
        for (int ni = 0; ni < 4; ++ni) {
            int cc = n0 + n_base + ni * 8 + (l & 3) * 2;
            float2 bv  = *(const float2*)&beta[cc];
            float2 x0  = *(const float2*)&X[(size_t)r0 * PP + cc];
            float2 x1  = *(const float2*)&X[(size_t)r1 * PP + cc];
            p0 = fmaf(acc[mi][ni][0] + bv.x, x0.x, p0);
            p0 = fmaf(acc[mi][ni][1] + bv.y, x0.y, p0);
            p1 = fmaf(acc[mi][ni][2] + bv.x, x1.x, p1);
            p1 = fmaf(acc[mi][ni][3] + bv.y, x1.y, p1);
        }
        // reduce over the 4 lanes sharing a row (low 2 lane bits)
        p0 += __shfl_xor_sync(0xffffffffu, p0, 1);
        p0 += __shfl_xor_sync(0xffffffffu, p0, 2);
        p1 += __shfl_xor_sync(0xffffffffu, p1, 1);
        p1 += __shfl_xor_sync(0xffffffffu, p1, 2);
        if ((l & 3) == 0) {
            sarr[wn * 128 + tr0] = p0;
            sarr[wn * 128 + tr1] = p1;
        }
    }
    __syncthreads();
    if (tid < 128) {
        float s = sarr[tid] + sarr[128 + tid] + sarr[256 + tid] + sarr[384 + tid];
        g_ypart[(size_t)bn * NROW + i0 + tid] = s;
    }
}

// ---------------------------------------------------------------------------
// Final: y[i] = beta0 + sum of 8 partials
// ---------------------------------------------------------------------------
__global__ void reduce_kernel(const float* __restrict__ beta0, float* __restrict__ y) {
    int i = blockIdx.x * blockDim.x + threadIdx.x;
    if (i >= NROW) return;
    float s = beta0[0];
#pragma unroll
    for (int g = 0; g < NSLOT; ++g) s += g_ypart[(size_t)g * NROW + i];
    y[i] = s;
}

extern "C" void kernel_launch(void* const* d_in, const int* in_sizes, int n_in,
                              void* d_out, int out_size) {
    const float* X     = (const float*)d_in[0];
    const float* beta0 = (const float*)d_in[1];
    const float* beta  = (const float*)d_in[2];
    const float* theta = (const float*)d_in[3];
    float* y = (float*)d_out;

    cudaFuncSetAttribute(gemm_rowdot_mma, cudaFuncAttributeMaxDynamicSharedMemorySize, SMEM_TOTAL);

    prep_kernel<<<XBLK + WBLK, 256>>>(X, theta);

    gemm_rowdot_mma<<<1024, 256, SMEM_TOTAL>>>(X, beta);

    reduce_kernel<<<(NROW + 255) / 256, 256>>>(beta0, y);
}

// round 11
// speedup vs baseline: 1.4078x; 1.0619x over previous
#include <cuda_runtime.h>
#include <cuda_bf16.h>
#include <cstdint>

#define PP 1024
#define NROW 16384
#define TILE_M 128
#define TILE_N 64
#define KC 64
#define NBN (PP / TILE_N)      // 16 n-tiles
#define NSLOT NBN              // 1 ypart slot per n-tile

// smem stage layout (bytes): A 128x64 bf16 hi/lo, B 64x64 bf16 hi/lo
#define AHI 0
#define ALO 16384
#define BHI 32768
#define BLO 40960
#define STAGE_BYTES 49152
#define SMEM_TOTAL (2 * STAGE_BYTES)   // 96 KB -> 2 CTAs/SM

// prep kernel split point: X-blocks then W-blocks
#define XBLK (NROW * PP / 8 / 256)     // 8192
#define WBLK (PP * PP / 4 / 256)       // 1024

// Scratch (static __device__ — no allocation allowed)
__device__ __align__(16) __nv_bfloat16 g_Xhi[(size_t)NROW * PP];
__device__ __align__(16) __nv_bfloat16 g_Xlo[(size_t)NROW * PP];
__device__ __align__(16) __nv_bfloat16 g_Whi[(size_t)PP * PP];   // W^T layout: [n][k]
__device__ __align__(16) __nv_bfloat16 g_Wlo[(size_t)PP * PP];
__device__ float g_ypart[(size_t)NSLOT * NROW];

// ---------------- helpers ----------------
__device__ __forceinline__ uint32_t smem_u32(const void* p) {
    uint32_t a;
    asm("{ .reg .u64 t; cvta.to.shared.u64 t, %1; cvt.u32.u64 %0, t; }" : "=r"(a) : "l"(p));
    return a;
}
// 128B rows of bf16 (64 elems). 16B chunk swizzle: chunk ^= (row & 7)
__device__ __forceinline__ uint32_t sw(int row, int ch) {
    return (uint32_t)(row * 128 + ((ch ^ (row & 7)) << 4));
}
__device__ __forceinline__ void cp16(uint32_t dst, const void* src) {
    asm volatile("cp.async.cg.shared.global [%0], [%1], 16;" :: "r"(dst), "l"(src) : "memory");
}
__device__ __forceinline__ void ldmx4(uint32_t* r, uint32_t addr) {
    asm volatile("ldmatrix.sync.aligned.m8n8.x4.shared.b16 {%0,%1,%2,%3}, [%4];"
                 : "=r"(r[0]), "=r"(r[1]), "=r"(r[2]), "=r"(r[3]) : "r"(addr));
}
__device__ __forceinline__ void mma16816(float* c, const uint32_t* a, const uint32_t* b) {
    asm volatile(
        "mma.sync.aligned.m16n8k16.row.col.f32.bf16.bf16.f32 "
        "{%0,%1,%2,%3}, {%4,%5,%6,%7}, {%8,%9}, {%0,%1,%2,%3};"
        : "+f"(c[0]), "+f"(c[1]), "+f"(c[2]), "+f"(c[3])
        : "r"(a[0]), "r"(a[1]), "r"(a[2]), "r"(a[3]), "r"(b[0]), "r"(b[1]));
}
__device__ __forceinline__ void split2(float a, float b, uint32_t& hi, uint32_t& lo) {
    __nv_bfloat16 h0 = __float2bfloat16(a);
    __nv_bfloat16 h1 = __float2bfloat16(b);
    __nv_bfloat16 l0 = __float2bfloat16(a - __bfloat162float(h0));
    __nv_bfloat16 l1 = __float2bfloat16(b - __bfloat162float(h1));
    hi = (uint32_t)__bfloat16_as_ushort(h0) | ((uint32_t)__bfloat16_as_ushort(h1) << 16);
    lo = (uint32_t)__bfloat16_as_ushort(l0) | ((uint32_t)__bfloat16_as_ushort(l1) << 16);
}

// ---------------------------------------------------------------------------
// Fused prep: blocks [0, XBLK) split X; blocks [XBLK, XBLK+WBLK) build W^T.
// ---------------------------------------------------------------------------
__global__ void prep_kernel(const float* __restrict__ X,
                            const float* __restrict__ theta) {
    if (blockIdx.x < XBLK) {
        size_t idx = (size_t)blockIdx.x * 256 + threadIdx.x;   // over N*P/8
        float4 v0 = reinterpret_cast<const float4*>(X)[idx * 2];
        float4 v1 = reinterpret_cast<const float4*>(X)[idx * 2 + 1];
        float f[8] = {v0.x, v0.y, v0.z, v0.w, v1.x, v1.y, v1.z, v1.w};
        uint32_t hi[4], lo[4];
#pragma unroll
        for (int q = 0; q < 4; ++q) split2(f[2 * q], f[2 * q + 1], hi[q], lo[q]);
        reinterpret_cast<uint4*>(g_Xhi)[idx] = make_uint4(hi[0], hi[1], hi[2], hi[3]);
        reinterpret_cast<uint4*>(g_Xlo)[idx] = make_uint4(lo[0], lo[1], lo[2], lo[3]);
    } else {
        int idx4 = (int)(blockIdx.x - XBLK) * 256 + threadIdx.x;  // over P*P/4
        int base = idx4 * 4;
        int n = base >> 10;
        int k0 = base & (PP - 1);     // 4 consecutive k, same n
        uint32_t hi[2], lo[2];
#pragma unroll
        for (int q = 0; q < 2; ++q) {
            float f[2];
#pragma unroll
            for (int e = 0; e < 2; ++e) {
                int k = k0 + q * 2 + e;
                f[e] = (n > k) ? theta[k * PP - ((k * (k + 1)) >> 1) + (n - k - 1)] : 0.0f;
            }
            split2(f[0], f[1], hi[q], lo[q]);
        }
        reinterpret_cast<uint2*>(g_Whi + base)[0] = make_uint2(hi[0], hi[1]);
        reinterpret_cast<uint2*>(g_Wlo + base)[0] = make_uint2(lo[0], lo[1]);
    }
}

// ---------------------------------------------------------------------------
// Main: bf16x3 mma.sync GEMM (128x64 tile, 2 CTAs/SM) + fused rowdot epilogue.
// Finer triangular skip: nch_eff = bn+1 (bn in 0..15). LPT heavy-first.
// ---------------------------------------------------------------------------
__global__ __launch_bounds__(256, 2)
void gemm_rowdot_mma(const float* __restrict__ X, const float* __restrict__ beta) {
    extern __shared__ char smem[];
    const uint32_t sbase = smem_u32(smem);
    const int tid = threadIdx.x;
    const int l = tid & 31;
    const int wid = tid >> 5;
    const int wm = wid & 1;        // 2 m-warps (64 rows each)
    const int wn = wid >> 1;       // 4 n-warps (16 cols each)
    const int m_base = wm * 64;
    const int n_base = wn * 16;

    // heavy-first decode: first 128 CTAs take bn=15, next 128 bn=14, ...
    const int bn = (NBN - 1) - (int)(blockIdx.x >> 7);
    const int bx = (int)(blockIdx.x & 127);
    const int i0 = bx * TILE_M;
    const int n0 = bn * TILE_N;
    const int nch_eff = bn + 1;    // chunks 0..bn (k0 < n0+64)

    float acc[4][2][4];            // [mi][ni][frag]
#pragma unroll
    for (int mi = 0; mi < 4; ++mi)
#pragma unroll
        for (int ni = 0; ni < 2; ++ni)
#pragma unroll
            for (int q = 0; q < 4; ++q) acc[mi][ni][q] = 0.0f;

    // --- async load of one stage ---
    auto load_stage = [&](int c) {
        const uint32_t stg = sbase + (uint32_t)(c & 1) * STAGE_BYTES;
        const int k0 = c * KC;
        // A: 128 rows x 8 ch -> 1024 slots, 4 iters
#pragma unroll
        for (int it = 0; it < 4; ++it) {
            int u = tid + it * 256;
            int row = u >> 3, ch = u & 7;
            uint32_t d = sw(row, ch);
            size_t asrc = (size_t)(i0 + row) * PP + k0 + ch * 8;
            cp16(stg + AHI + d, g_Xhi + asrc);
            cp16(stg + ALO + d, g_Xlo + asrc);
        }
        // B: 64 rows x 8 ch -> 512 slots, 2 iters
#pragma unroll
        for (int it = 0; it < 2; ++it) {
            int u = tid + it * 256;
            int row = u >> 3, ch = u & 7;
            uint32_t d = sw(row, ch);
            size_t bsrc = (size_t)(n0 + row) * PP + k0 + ch * 8;
            cp16(stg + BHI + d, g_Whi + bsrc);
            cp16(stg + BLO + d, g_Wlo + bsrc);
        }
        asm volatile("cp.async.commit_group;" ::: "memory");
    };

    load_stage(0);

    for (int c = 0; c < nch_eff; ++c) {
        if (c + 1 < nch_eff) {
            load_stage(c + 1);
            asm volatile("cp.async.wait_group 1;" ::: "memory");
        } else {
            asm volatile("cp.async.wait_group 0;" ::: "memory");
        }
        __syncthreads();

        const uint32_t stg = sbase + (uint32_t)(c & 1) * STAGE_BYTES;
#pragma unroll
        for (int ks = 0; ks < 4; ++ks) {
            uint32_t ahi[4][4], alo[4][4], bhi[2][2], blo[2][2];
            // A fragments: lanes 0-15 rows r (k-lo half), lanes 16-31 (k-hi)
            {
                int r = l & 15, kh = l >> 4;
                int ch = ks * 2 + kh;
#pragma unroll
                for (int mi = 0; mi < 4; ++mi) {
                    uint32_t ad = sw(m_base + mi * 16 + r, ch);
                    ldmx4(ahi[mi], stg + AHI + ad);
                    ldmx4(alo[mi], stg + ALO + ad);
                }
            }
            // B fragments: one ldmatrix.x4 covers 16 n-rows x 16 k
            {
                int nr_off = ((l >> 4) << 3) + (l & 7);
                int ch = ks * 2 + ((l >> 3) & 1);
                uint32_t bd = sw(n_base + nr_off, ch);
                uint32_t r4[4];
                ldmx4(r4, stg + BHI + bd);
                bhi[0][0] = r4[0]; bhi[0][1] = r4[1];
                bhi[1][0] = r4[2]; bhi[1][1] = r4[3];
                ldmx4(r4, stg + BLO + bd);
                blo[0][0] = r4[0]; blo[0][1] = r4[1];
                blo[1][0] = r4[2]; blo[1][1] = r4[3];
            }
#pragma unroll
            for (int mi = 0; mi < 4; ++mi)
#pragma unroll
                for (int ni = 0; ni < 2; ++ni) {
                    mma16816(acc[mi][ni], ahi[mi], bhi[ni]);
                    mma16816(acc[mi][ni], ahi[mi], blo[ni]);
                    mma16816(acc[mi][ni], alo[mi], bhi[ni]);
                }
        }
        __syncthreads();
    }

    // --- fused epilogue: part_r = sum_c (C[r][c] + beta[c]) * X[r][c] ---
    float* sarr = (float*)smem;    // 4*128 floats (safe: final loop sync passed)
#pragma unroll
    for (int mi = 0; mi < 4; ++mi) {
        int tr0 = m_base + mi * 16 + (l >> 2);
        int tr1 = tr0 + 8;
        int r0 = i0 + tr0;
        int r1 = i0 + tr1;
        float p0 = 0.0f, p1 = 0.0f;
#pragma unroll
        for (int ni = 0; ni < 2; ++ni) {
            int cc = n0 + n_base + ni * 8 + (l & 3) * 2;
            float2 bv  = *(const float2*)&beta[cc];
            float2 x0  = *(const float2*)&X[(size_t)r0 * PP + cc];
            float2 x1  = *(const float2*)&X[(size_t)r1 * PP + cc];
            p0 = fmaf(acc[mi][ni][0] + bv.x, x0.x, p0);
            p0 = fmaf(acc[mi][ni][1] + bv.y, x0.y, p0);
            p1 = fmaf(acc[mi][ni][2] + bv.x, x1.x, p1);
            p1 = fmaf(acc[mi][ni][3] + bv.y, x1.y, p1);
        }
        p0 += __shfl_xor_sync(0xffffffffu, p0, 1);
        p0 += __shfl_xor_sync(0xffffffffu, p0, 2);
        p1 += __shfl_xor_sync(0xffffffffu, p1, 1);
        p1 += __shfl_xor_sync(0xffffffffu, p1, 2);
        if ((l & 3) == 0) {
            sarr[wn * 128 + tr0] = p0;
            sarr[wn * 128 + tr1] = p1;
        }
    }
    __syncthreads();
    if (tid < 128) {
        float s = sarr[tid] + sarr[128 + tid] + sarr[256 + tid] + sarr[384 + tid];
        g_ypart[(size_t)bn * NROW + i0 + tid] = s;
    }
}

// ---------------------------------------------------------------------------
// Final: y[i] = beta0 + sum of 16 partials
// ---------------------------------------------------------------------------
__global__ void reduce_kernel(const float* __restrict__ beta0, float* __restrict__ y) {
    int i = blockIdx.x * blockDim.x + threadIdx.x;
    if (i >= NROW) return;
    float s = beta0[0];
#pragma unroll
    for (int g = 0; g < NSLOT; ++g) s += g_ypart[(size_t)g * NROW + i];
    y[i] = s;
}

extern "C" void kernel_launch(void* const* d_in, const int* in_sizes, int n_in,
                              void* d_out, int out_size) {
    const float* X     = (const float*)d_in[0];
    const float* beta0 = (const float*)d_in[1];
    const float* beta  = (const float*)d_in[2];
    const float* theta = (const float*)d_in[3];
    float* y = (float*)d_out;

    cudaFuncSetAttribute(gemm_rowdot_mma, cudaFuncAttributeMaxDynamicSharedMemorySize, SMEM_TOTAL);

    prep_kernel<<<XBLK + WBLK, 256>>>(X, theta);

    gemm_rowdot_mma<<<NBN * 128, 256, SMEM_TOTAL>>>(X, beta);

    reduce_kernel<<<(NROW + 255) / 256, 256>>>(beta0, y);
}